// round 2
// baseline (speedup 1.0000x reference)
#include <cuda_runtime.h>

// AdderVDSR collapses analytically:
//   - adder_conv output = -sum|...| <= 0 (strictly < 0), no bias, relu => exact 0.0
//   - zeros propagate through all 16 adder layers
//   - out = conv3(0, out_w, out_b) + residual = out_b + pixel_shuffle(conv3(x, up_w, up_b), 2)
// So the whole net is a 3->12 3x3 conv (pad 1) on [2,3,128,128], pixel shuffle r=2,
// plus per-channel out_b. Fused into one kernel.

#define B   2
#define CIN 3
#define H   128
#define W   128
#define OC  12   // 4 * CIN

__global__ __launch_bounds__(256) void adder_vdsr_collapsed_kernel(
    const float* __restrict__ x,      // [B, 3, 128, 128]
    const float* __restrict__ up_w,   // [12, 3, 3, 3]
    const float* __restrict__ up_b,   // [12]
    const float* __restrict__ out_b,  // [3]
    float* __restrict__ out)          // [B, 3, 256, 256]
{
    __shared__ float sw[OC * CIN * 9];   // 324
    __shared__ float sb[OC];
    __shared__ float sob[CIN];

    int tid = threadIdx.x;
    for (int i = tid; i < OC * CIN * 9; i += blockDim.x) sw[i] = up_w[i];
    if (tid < OC)  sb[tid]  = up_b[tid];
    if (tid < CIN) sob[tid] = out_b[tid];
    __syncthreads();

    int idx = blockIdx.x * blockDim.x + tid;          // over B*H*W = 32768
    if (idx >= B * H * W) return;
    int w = idx & (W - 1);
    int h = (idx >> 7) & (H - 1);
    int b = idx >> 14;

    float acc[OC];
#pragma unroll
    for (int o = 0; o < OC; o++) acc[o] = sb[o];

    const float* xb = x + b * CIN * H * W;
#pragma unroll
    for (int ic = 0; ic < CIN; ic++) {
        const float* xc = xb + ic * H * W;
#pragma unroll
        for (int dy = 0; dy < 3; dy++) {
            int yy = h + dy - 1;
            bool yok = ((unsigned)yy < (unsigned)H);
#pragma unroll
            for (int dx = 0; dx < 3; dx++) {
                int xx = w + dx - 1;
                float v = (yok && ((unsigned)xx < (unsigned)W)) ? xc[yy * W + xx] : 0.0f;
                int wbase = (ic * 3 + dy) * 3 + dx;
#pragma unroll
                for (int o = 0; o < OC; o++)
                    acc[o] = fmaf(v, sw[o * 27 + wbase], acc[o]);
            }
        }
    }

    // Pixel shuffle write + out_b: out[b][c][2h+i][2w+j] = acc[4c+2i+j] + out_b[c]
    float* ob = out + b * CIN * (2 * H) * (2 * W);
#pragma unroll
    for (int c = 0; c < CIN; c++) {
        float obias = sob[c];
        float* oc_base = ob + c * (2 * H) * (2 * W);
#pragma unroll
        for (int i = 0; i < 2; i++) {
            float2 v2;
            v2.x = acc[c * 4 + i * 2 + 0] + obias;
            v2.y = acc[c * 4 + i * 2 + 1] + obias;
            *reinterpret_cast<float2*>(oc_base + (2 * h + i) * (2 * W) + 2 * w) = v2;
        }
    }
}

extern "C" void kernel_launch(void* const* d_in, const int* in_sizes, int n_in,
                              void* d_out, int out_size)
{
    // metadata order: x, up_w, up_b, in_w, in_b, adder_w, out_w, out_b
    const float* x     = (const float*)d_in[0];
    const float* up_w  = (const float*)d_in[1];
    const float* up_b  = (const float*)d_in[2];
    const float* out_b = (const float*)d_in[7];
    float* out = (float*)d_out;

    int total = B * H * W;                 // 32768 threads
    int threads = 256;
    int blocks = (total + threads - 1) / threads;   // 128
    adder_vdsr_collapsed_kernel<<<blocks, threads>>>(x, up_w, up_b, out_b, out);
}

// round 3
// speedup vs baseline: 1.2560x; 1.2560x over previous
#include <cuda_runtime.h>

// AdderVDSR collapses analytically (verified R1, rel_err 1.2e-7):
//   adder_conv = -sum|..| < 0, no bias => relu -> exact 0, propagates through all
//   16 layers => out = out_b + pixel_shuffle(conv3(x, up_w, up_b), 2).
// R2: smem-staged rows + f32x2 packed FMA + pixel-shuffle-native packed stores.

#define Bn  2
#define CIN 3
#define Hn  128
#define Wn  128
#define OC  12
#define XSS 130   // padded row stride: 128 + 2 zero columns

__device__ __forceinline__ unsigned long long pack2(float lo, float hi) {
    unsigned long long r;
    asm("mov.b64 %0, {%1, %2};" : "=l"(r) : "f"(lo), "f"(hi));
    return r;
}
__device__ __forceinline__ void unpack2(unsigned long long v, float& lo, float& hi) {
    asm("mov.b64 {%0, %1}, %2;" : "=f"(lo), "=f"(hi) : "l"(v));
}
__device__ __forceinline__ unsigned long long fma2(unsigned long long a,
                                                   unsigned long long b,
                                                   unsigned long long c) {
    unsigned long long d;
    asm("fma.rn.f32x2 %0, %1, %2, %3;" : "=l"(d) : "l"(a), "l"(b), "l"(c));
    return d;
}

__global__ __launch_bounds__(128) void adder_vdsr_r2_kernel(
    const float* __restrict__ x,      // [2, 3, 128, 128]
    const float* __restrict__ up_w,   // [12, 3, 3, 3]
    const float* __restrict__ up_b,   // [12]
    const float* __restrict__ out_b,  // [3]
    float* __restrict__ out)          // [2, 3, 256, 256]
{
    __shared__ __align__(16) float ws[27 * OC];   // transposed: ws[k*12 + o]
    __shared__ __align__(8)  float sb[OC];
    __shared__ float sob[4];
    __shared__ float xs[CIN * 3 * XSS];           // 3 ch x 3 halo rows, zero-padded cols

    int t  = threadIdx.x;                         // w position, 0..127
    int bh = blockIdx.x;                          // over B*H = 256
    int h  = bh & (Hn - 1);
    int b  = bh >> 7;

    // ---- fill weights (transposed so adjacent oc pair -> one 8B word) ----
    for (int i = t; i < 27 * OC; i += 128) {
        int o  = i / 27;
        int kk = i - o * 27;
        ws[kk * OC + o] = up_w[i];
    }
    if (t < OC)  sb[t]  = up_b[t];
    if (t < CIN) sob[t] = out_b[t];

    // ---- fill input halo rows (9 coalesced LDG per thread) ----
    const float* xb = x + b * (CIN * Hn * Wn);
#pragma unroll
    for (int ic = 0; ic < CIN; ic++) {
#pragma unroll
        for (int dy = 0; dy < 3; dy++) {
            int yy = h + dy - 1;
            float v = 0.0f;
            if ((unsigned)yy < (unsigned)Hn) v = xb[ic * Hn * Wn + yy * Wn + t];
            float* row = xs + (ic * 3 + dy) * XSS;
            row[1 + t] = v;
            if (t == 0) { row[0] = 0.0f; row[XSS - 1] = 0.0f; }
        }
    }
    __syncthreads();

    // ---- gather 3x3x3 neighborhood from smem ----
    float x27[27];
#pragma unroll
    for (int ic = 0; ic < CIN; ic++)
#pragma unroll
        for (int dy = 0; dy < 3; dy++) {
            const float* row = xs + (ic * 3 + dy) * XSS + t;   // row[dx], dx in 0..2 == w-1..w+1
#pragma unroll
            for (int dx = 0; dx < 3; dx++)
                x27[(ic * 3 + dy) * 3 + dx] = row[dx];
        }

    // ---- packed f32x2 accumulation over 12 output channels (6 pairs) ----
    unsigned long long acc2[6];
    const unsigned long long* sb2 = reinterpret_cast<const unsigned long long*>(sb);
#pragma unroll
    for (int j = 0; j < 6; j++) acc2[j] = sb2[j];

    const unsigned long long* ws2 = reinterpret_cast<const unsigned long long*>(ws);
#pragma unroll
    for (int kk = 0; kk < 27; kk++) {
        unsigned long long vv = pack2(x27[kk], x27[kk]);
#pragma unroll
        for (int j = 0; j < 6; j++)
            acc2[j] = fma2(vv, ws2[kk * 6 + j], acc2[j]);
    }

    // ---- pixel-shuffle store: out[b][c][2h+i][2w+j] = acc[4c+2i+j] + out_b[c]
    // packed pair (j=0,j=1) is exactly acc2[2c+i]
    float* ob = out + b * (CIN * 2 * Hn * 2 * Wn);
#pragma unroll
    for (int c = 0; c < CIN; c++) {
        float obias = sob[c];
#pragma unroll
        for (int i = 0; i < 2; i++) {
            float lo, hi;
            unpack2(acc2[2 * c + i], lo, hi);
            float2 v2 = make_float2(lo + obias, hi + obias);
            *reinterpret_cast<float2*>(ob + (c * 2 * Hn + 2 * h + i) * (2 * Wn) + 2 * t) = v2;
        }
    }
}

extern "C" void kernel_launch(void* const* d_in, const int* in_sizes, int n_in,
                              void* d_out, int out_size)
{
    // metadata order: x, up_w, up_b, in_w, in_b, adder_w, out_w, out_b
    const float* x     = (const float*)d_in[0];
    const float* up_w  = (const float*)d_in[1];
    const float* up_b  = (const float*)d_in[2];
    const float* out_b = (const float*)d_in[7];
    float* out = (float*)d_out;

    adder_vdsr_r2_kernel<<<Bn * Hn, 128>>>(x, up_w, up_b, out_b, out);
}